// round 4
// baseline (speedup 1.0000x reference)
#include <cuda_runtime.h>
#include <math.h>

// Problem constants (fixed by the dataset)
#define NU 60000
#define NI 40000
#define NN 100000     // NU + NI
#define NE 500000
#define D  64
#define NF 4
#define NBLK 98       // ceil(NN/1024) for the scan

// ---------------- static device scratch ----------------
__device__ float  g_ego0[NN * D];
__device__ float  g_ego1[NN * D];
__device__ float  g_all [NN * D];
__device__ float  g_tv0 [NN * D];    // tv double buffer (fix for round-2/3 hazard)
__device__ float  g_tv1 [NN * D];
__device__ float4 g_S4  [NE];        // raw S, edge-major [NE,4]
__device__ float4 g_Ssm4[NE];        // softmaxed S, edge-major
__device__ float  g_rn  [NN * NF];   // per-node per-factor 1/||xn||
__device__ float  g_dinv[NN];
__device__ int    g_deg [NN];
__device__ int    g_rowstart[NN + 1];
__device__ int    g_cnt [NN];
__device__ int    g_blocksum[NBLK];
__device__ float4 g_adj [2 * NE];    // {src, eid, enorm, flag}

// ---------------- setup kernels ----------------

__global__ void k_initego(const float* __restrict__ u, const float* __restrict__ it) {
    int i = blockIdx.x * blockDim.x + threadIdx.x;
    if (i >= NN * D) return;
    float v = (i < NU * D) ? u[i] : it[i - NU * D];
    g_ego0[i] = v;
    g_all[i]  = v;
}

// transpose input S [4,NE] -> [NE,4]
__global__ void k_transS_in(const float* __restrict__ S) {
    int j = blockIdx.x * blockDim.x + threadIdx.x;
    if (j >= NE) return;
    g_S4[j] = make_float4(S[j], S[NE + j], S[2 * NE + j], S[3 * NE + j]);
}

__global__ void k_deg(const int* __restrict__ ei) {
    int j = blockIdx.x * blockDim.x + threadIdx.x;
    if (j >= NE) return;
    atomicAdd(&g_deg[ei[j]], 1);
    atomicAdd(&g_deg[ei[NE + j]], 1);
}

__global__ void k_dinv() {
    int n = blockIdx.x * blockDim.x + threadIdx.x;
    if (n >= NN) return;
    int d = g_deg[n];
    g_dinv[n] = (d > 0) ? (1.0f / sqrtf((float)d)) : 0.0f;
}

// per-block sums of deg
__global__ void k_partial() {
    __shared__ int sh[1024];
    int t = threadIdx.x, n = blockIdx.x * 1024 + t;
    sh[t] = (n < NN) ? g_deg[n] : 0;
    __syncthreads();
    for (int o = 512; o > 0; o >>= 1) {
        if (t < o) sh[t] += sh[t + o];
        __syncthreads();
    }
    if (t == 0) g_blocksum[blockIdx.x] = sh[0];
}

// serial exclusive scan of NBLK block sums (tiny)
__global__ void k_scanblocks() {
    int acc = 0;
    for (int b = 0; b < NBLK; b++) {
        int v = g_blocksum[b];
        g_blocksum[b] = acc;
        acc += v;
    }
    g_rowstart[NN] = 2 * NE;
}

// per-block exclusive scan -> rowstart
__global__ void k_offsets() {
    __shared__ int sh[1024];
    int t = threadIdx.x, n = blockIdx.x * 1024 + t;
    int v = (n < NN) ? g_deg[n] : 0;
    sh[t] = v;
    __syncthreads();
    for (int o = 1; o < 1024; o <<= 1) {
        int x = (t >= o) ? sh[t - o] : 0;
        __syncthreads();
        sh[t] += x;
        __syncthreads();
    }
    if (n < NN) g_rowstart[n] = g_blocksum[blockIdx.x] + sh[t] - v;
}

// fill CSR adjacency: both directions of every edge
__global__ void k_fill(const int* __restrict__ ei) {
    int d = blockIdx.x * blockDim.x + threadIdx.x;
    if (d >= 2 * NE) return;
    int j   = (d < NE) ? d : d - NE;
    int fwd = (d < NE) ? 1 : 0;            // forward copy writes Ssm exactly once
    int r = ei[j], c = ei[NE + j];
    int src = fwd ? r : c;
    int dst = fwd ? c : r;
    int pos = g_rowstart[dst] + atomicAdd(&g_cnt[dst], 1);
    g_adj[pos] = make_float4(__int_as_float(src), __int_as_float(j),
                             g_dinv[src] * g_dinv[dst], __int_as_float(fwd));
}

// tv for layer 0 from the initial ego (warp per node)
__global__ void k_tv0() {
    int gw = (blockIdx.x * blockDim.x + threadIdx.x) >> 5;
    if (gw >= NN) return;
    int lane = threadIdx.x & 31;
    float2 a = reinterpret_cast<const float2*>(g_ego0 + (size_t)gw * D)[lane];
    float ss = a.x * a.x + a.y * a.y;
    ss += __shfl_xor_sync(0xFFFFFFFF, ss, 1);
    ss += __shfl_xor_sync(0xFFFFFFFF, ss, 2);
    ss += __shfl_xor_sync(0xFFFFFFFF, ss, 4);
    float rinv = 1.0f / fmaxf(sqrtf(ss), 1e-12f);
    float2 o;
    o.x = tanhf(a.x * rinv);
    o.y = tanhf(a.y * rinv);
    reinterpret_cast<float2*>(g_tv0 + (size_t)gw * D)[lane] = o;
}

// ---------------- main iteration kernels ----------------

// CSR conv, one warp per destination node. Fuses: softmax(S), message
// accumulation, rn computation, and (LAST) all_embs accumulation + NEXT
// layer's tv written into tv_next (double buffer — current layer's k_score
// still reads the current tv).
template <bool LAST>
__global__ void k_conv(const float* __restrict__ ego, float* __restrict__ xn,
                       float* __restrict__ tv_next) {
    int gw = (blockIdx.x * blockDim.x + threadIdx.x) >> 5;
    if (gw >= NN) return;
    int lane = threadIdx.x & 31;
    int kf = lane >> 3;                     // factor index of this lane group
    int s = g_rowstart[gw], e = g_rowstart[gw + 1];

    float2 acc = make_float2(0.0f, 0.0f);

    // software pipeline: (adj, S) for i+1 loads during iteration i
    float4 a0 = make_float4(0, 0, 0, 0), s0 = make_float4(0, 0, 0, 0);
    if (s < e) {
        a0 = g_adj[s];
        s0 = g_S4[__float_as_int(a0.y)];
    }
    for (int i = s; i < e; i++) {
        float4 a1 = a0, s1 = s0;
        if (i + 1 < e) {
            a1 = g_adj[i + 1];
            s1 = g_S4[__float_as_int(a1.y)];
        }
        int   nbr  = __float_as_int(a0.x);
        int   eid  = __float_as_int(a0.y);
        float en   = a0.z;
        int   fwd  = __float_as_int(a0.w);
        // start gather early
        float2 v = reinterpret_cast<const float2*>(ego + (size_t)nbr * D)[lane];
        // softmax over the 4 factors (all lanes redundantly, no shuffles)
        float m  = fmaxf(fmaxf(s0.x, s0.y), fmaxf(s0.z, s0.w));
        float e0 = expf(s0.x - m), e1 = expf(s0.y - m);
        float e2 = expf(s0.z - m), e3 = expf(s0.w - m);
        float r  = 1.0f / (e0 + e1 + e2 + e3);
        float4 sm = make_float4(e0 * r, e1 * r, e2 * r, e3 * r);
        if (fwd && lane == 0) g_Ssm4[eid] = sm;
        float smk = (kf == 0) ? sm.x : (kf == 1) ? sm.y : (kf == 2) ? sm.z : sm.w;
        float w = en * smk;
        acc.x += w * v.x;
        acc.y += w * v.y;
        a0 = a1; s0 = s1;
    }

    reinterpret_cast<float2*>(xn + (size_t)gw * D)[lane] = acc;

    // per-factor inverse norm (groups of 8 lanes)
    float ss = acc.x * acc.x + acc.y * acc.y;
    ss += __shfl_xor_sync(0xFFFFFFFF, ss, 1);
    ss += __shfl_xor_sync(0xFFFFFFFF, ss, 2);
    ss += __shfl_xor_sync(0xFFFFFFFF, ss, 4);
    float rinv = 1.0f / fmaxf(sqrtf(ss), 1e-12f);
    if ((lane & 7) == 0) g_rn[gw * NF + kf] = rinv;

    if (LAST) {
        float2* ap = reinterpret_cast<float2*>(g_all + (size_t)gw * D) + lane;
        float2 av = *ap;
        av.x += acc.x; av.y += acc.y;
        *ap = av;
        float2 t;
        t.x = tanhf(acc.x * rinv);
        t.y = tanhf(acc.y * rinv);
        reinterpret_cast<float2*>(tv_next + (size_t)gw * D)[lane] = t;
    }
}

// routing-score update, one warp per original edge:
// S[j] = Ssm[j] + rn[row]_k * dot(xn[row,k,:], tv[col,k,:])
__global__ void k_score(const float* __restrict__ xn, const float* __restrict__ tv,
                        const int* __restrict__ ei) {
    int gw = (blockIdx.x * blockDim.x + threadIdx.x) >> 5;
    if (gw >= NE) return;
    int lane = threadIdx.x & 31;
    int r = ei[gw];
    int c = ei[NE + gw];
    float2 a = reinterpret_cast<const float2*>(xn + (size_t)r * D)[lane];
    float2 b = reinterpret_cast<const float2*>(tv + (size_t)c * D)[lane];
    float p = a.x * b.x + a.y * b.y;
    p += __shfl_xor_sync(0xFFFFFFFF, p, 1);
    p += __shfl_xor_sync(0xFFFFFFFF, p, 2);
    p += __shfl_xor_sync(0xFFFFFFFF, p, 4);
    float p0 = __shfl_sync(0xFFFFFFFF, p, 0);
    float p1 = __shfl_sync(0xFFFFFFFF, p, 8);
    float p2 = __shfl_sync(0xFFFFFFFF, p, 16);
    float p3 = __shfl_sync(0xFFFFFFFF, p, 24);
    if (lane == 0) {
        float4 rn = *reinterpret_cast<const float4*>(g_rn + (size_t)r * NF);
        float4 sv = g_Ssm4[gw];
        sv.x += p0 * rn.x;
        sv.y += p1 * rn.y;
        sv.z += p2 * rn.z;
        sv.w += p3 * rn.w;
        g_S4[gw] = sv;
    }
}

// output S transpose [NE,4] -> [4,NE]
__global__ void k_transS_out(float* __restrict__ outS) {
    int j = blockIdx.x * blockDim.x + threadIdx.x;
    if (j >= NE) return;
    float4 s = g_S4[j];
    outS[j]          = s.x;
    outS[NE + j]     = s.y;
    outS[2 * NE + j] = s.z;
    outS[3 * NE + j] = s.w;
}

// ---------------- host orchestration ----------------

extern "C" void kernel_launch(void* const* d_in, const int* in_sizes, int n_in,
                              void* d_out, int out_size) {
    const float* user = (const float*)d_in[0];
    const float* item = (const float*)d_in[1];
    const float* Sin  = (const float*)d_in[2];
    const int*   ei   = (const int*)d_in[3];
    float* out = (float*)d_out;

    void *p_deg, *p_cnt, *p_ego0, *p_ego1, *p_all, *p_tv0, *p_tv1;
    cudaGetSymbolAddress(&p_deg,  g_deg);
    cudaGetSymbolAddress(&p_cnt,  g_cnt);
    cudaGetSymbolAddress(&p_ego0, g_ego0);
    cudaGetSymbolAddress(&p_ego1, g_ego1);
    cudaGetSymbolAddress(&p_all,  g_all);
    cudaGetSymbolAddress(&p_tv0,  g_tv0);
    cudaGetSymbolAddress(&p_tv1,  g_tv1);

    const int T = 256;
    const int gElem  = (NN * D + T - 1) / T;
    const int gNode  = (NN + T - 1) / T;
    const int gEdge  = (NE + T - 1) / T;
    const int gDir   = (2 * NE + T - 1) / T;
    const int gEdgeW = (NE * 32 + T - 1) / T;
    const int gNodeW = (NN * 32 + T - 1) / T;

    // ---- setup ----
    cudaMemsetAsync(p_deg, 0, NN * sizeof(int), 0);
    cudaMemsetAsync(p_cnt, 0, NN * sizeof(int), 0);
    k_initego<<<gElem, T>>>(user, item);
    k_transS_in<<<gEdge, T>>>(Sin);
    k_deg<<<gEdge, T>>>(ei);
    k_dinv<<<gNode, T>>>();
    k_partial<<<NBLK, 1024>>>();
    k_scanblocks<<<1, 1>>>();
    k_offsets<<<NBLK, 1024>>>();
    k_fill<<<gDir, T>>>(ei);
    k_tv0<<<gNodeW, T>>>();

    // ---- 2 layers x 2 routing iterations ----
    float* ego = (float*)p_ego0;
    float* xn  = (float*)p_ego1;
    float* tv  = (float*)p_tv0;
    float* tvn = (float*)p_tv1;
    for (int layer = 0; layer < 2; layer++) {
        for (int it = 0; it < 2; it++) {
            if (it == 1)
                k_conv<true><<<gNodeW, T>>>(ego, xn, tvn);  // writes NEXT tv buffer
            else
                k_conv<false><<<gNodeW, T>>>(ego, xn, tvn);
            k_score<<<gEdgeW, T>>>(xn, tv, ei);             // reads CURRENT tv
        }
        float* t = ego; ego = xn; xn = t;
        t = tv; tv = tvn; tvn = t;
    }

    // ---- output: [user_all | item_all | S(4,NE)] ----
    cudaMemcpyAsync(out, p_all, (size_t)NN * D * sizeof(float),
                    cudaMemcpyDeviceToDevice, 0);
    k_transS_out<<<gEdge, T>>>(out + (size_t)NN * D);
}

// round 5
// speedup vs baseline: 1.3017x; 1.3017x over previous
#include <cuda_runtime.h>
#include <math.h>

// Problem constants (fixed by the dataset)
#define NU 60000
#define NI 40000
#define NN 100000     // NU + NI
#define NE 500000
#define D  64
#define NF 4
#define NBLK 98       // ceil(NN/1024) for the scan

// ---------------- static device scratch ----------------
__device__ float  g_ego0[NN * D];
__device__ float  g_ego1[NN * D];
__device__ float  g_all [NN * D];
__device__ float  g_tv0 [NN * D];    // tv double buffer
__device__ float  g_tv1 [NN * D];
__device__ float4 g_S4  [NE];        // raw S, edge-major [NE,4]
__device__ float4 g_Ssm4[NE];        // softmaxed S, edge-major
__device__ float  g_rn  [NN * NF];   // per-node per-factor 1/||xn||
__device__ float  g_dinv[NN];
__device__ int    g_deg [NN];
__device__ int    g_rowstart[NN + 1];
__device__ int    g_cnt [NN];
__device__ int    g_blocksum[NBLK];
__device__ float4 g_adj [2 * NE];    // {src, eid, enorm, unused}

// ---------------- setup kernels ----------------

__global__ void k_initego(const float* __restrict__ u, const float* __restrict__ it) {
    int i = blockIdx.x * blockDim.x + threadIdx.x;
    if (i >= NN * D) return;
    float v = (i < NU * D) ? u[i] : it[i - NU * D];
    g_ego0[i] = v;
    g_all[i]  = v;
}

// transpose input S [4,NE] -> [NE,4]
__global__ void k_transS_in(const float* __restrict__ S) {
    int j = blockIdx.x * blockDim.x + threadIdx.x;
    if (j >= NE) return;
    g_S4[j] = make_float4(S[j], S[NE + j], S[2 * NE + j], S[3 * NE + j]);
}

__global__ void k_deg(const int* __restrict__ ei) {
    int j = blockIdx.x * blockDim.x + threadIdx.x;
    if (j >= NE) return;
    atomicAdd(&g_deg[ei[j]], 1);
    atomicAdd(&g_deg[ei[NE + j]], 1);
}

__global__ void k_dinv() {
    int n = blockIdx.x * blockDim.x + threadIdx.x;
    if (n >= NN) return;
    int d = g_deg[n];
    g_dinv[n] = (d > 0) ? (1.0f / sqrtf((float)d)) : 0.0f;
}

// per-block sums of deg
__global__ void k_partial() {
    __shared__ int sh[1024];
    int t = threadIdx.x, n = blockIdx.x * 1024 + t;
    sh[t] = (n < NN) ? g_deg[n] : 0;
    __syncthreads();
    for (int o = 512; o > 0; o >>= 1) {
        if (t < o) sh[t] += sh[t + o];
        __syncthreads();
    }
    if (t == 0) g_blocksum[blockIdx.x] = sh[0];
}

// serial exclusive scan of NBLK block sums (tiny)
__global__ void k_scanblocks() {
    int acc = 0;
    for (int b = 0; b < NBLK; b++) {
        int v = g_blocksum[b];
        g_blocksum[b] = acc;
        acc += v;
    }
    g_rowstart[NN] = 2 * NE;
}

// per-block exclusive scan -> rowstart
__global__ void k_offsets() {
    __shared__ int sh[1024];
    int t = threadIdx.x, n = blockIdx.x * 1024 + t;
    int v = (n < NN) ? g_deg[n] : 0;
    sh[t] = v;
    __syncthreads();
    for (int o = 1; o < 1024; o <<= 1) {
        int x = (t >= o) ? sh[t - o] : 0;
        __syncthreads();
        sh[t] += x;
        __syncthreads();
    }
    if (n < NN) g_rowstart[n] = g_blocksum[blockIdx.x] + sh[t] - v;
}

// fill CSR adjacency: both directions of every edge
__global__ void k_fill(const int* __restrict__ ei) {
    int d = blockIdx.x * blockDim.x + threadIdx.x;
    if (d >= 2 * NE) return;
    int j = (d < NE) ? d : d - NE;
    int r = ei[j], c = ei[NE + j];
    int src = (d < NE) ? r : c;
    int dst = (d < NE) ? c : r;
    int pos = g_rowstart[dst] + atomicAdd(&g_cnt[dst], 1);
    g_adj[pos] = make_float4(__int_as_float(src), __int_as_float(j),
                             g_dinv[src] * g_dinv[dst], 0.0f);
}

// tv for layer 0 from the initial ego (warp per node)
__global__ void k_tv0() {
    int gw = (blockIdx.x * blockDim.x + threadIdx.x) >> 5;
    if (gw >= NN) return;
    int lane = threadIdx.x & 31;
    float2 a = reinterpret_cast<const float2*>(g_ego0 + (size_t)gw * D)[lane];
    float ss = a.x * a.x + a.y * a.y;
    ss += __shfl_xor_sync(0xFFFFFFFF, ss, 1);
    ss += __shfl_xor_sync(0xFFFFFFFF, ss, 2);
    ss += __shfl_xor_sync(0xFFFFFFFF, ss, 4);
    float rinv = 1.0f / fmaxf(sqrtf(ss), 1e-12f);
    float2 o;
    o.x = tanhf(a.x * rinv);
    o.y = tanhf(a.y * rinv);
    reinterpret_cast<float2*>(g_tv0 + (size_t)gw * D)[lane] = o;
}

// ---------------- main iteration kernels ----------------

// softmax over 4 factors, once per edge (E threads total, NOT per-lane in conv)
__global__ void k_softmax() {
    int j = blockIdx.x * blockDim.x + threadIdx.x;
    if (j >= NE) return;
    float4 s = g_S4[j];
    float m  = fmaxf(fmaxf(s.x, s.y), fmaxf(s.z, s.w));
    float e0 = expf(s.x - m), e1 = expf(s.y - m);
    float e2 = expf(s.z - m), e3 = expf(s.w - m);
    float r  = 1.0f / (e0 + e1 + e2 + e3);
    g_Ssm4[j] = make_float4(e0 * r, e1 * r, e2 * r, e3 * r);
}

// CSR conv, one warp per destination node. Loads precomputed softmax(S).
// Fuses: message accumulation, rn, and (LAST) all_embs accumulation +
// NEXT layer's tv into tv_next (double buffer).
template <bool LAST>
__global__ void k_conv(const float* __restrict__ ego, float* __restrict__ xn,
                       float* __restrict__ tv_next) {
    int gw = (blockIdx.x * blockDim.x + threadIdx.x) >> 5;
    if (gw >= NN) return;
    int lane = threadIdx.x & 31;
    int kf = lane >> 3;                     // factor index of this lane group
    int s = g_rowstart[gw], e = g_rowstart[gw + 1];

    float2 acc = make_float2(0.0f, 0.0f);

    // software pipeline: (adj, Ssm) for i+1 loads during iteration i
    float4 a0 = make_float4(0, 0, 0, 0), s0 = make_float4(0, 0, 0, 0);
    if (s < e) {
        a0 = g_adj[s];
        s0 = g_Ssm4[__float_as_int(a0.y)];
    }
    for (int i = s; i < e; i++) {
        float4 a1 = a0, s1 = s0;
        if (i + 1 < e) {
            a1 = g_adj[i + 1];
            s1 = g_Ssm4[__float_as_int(a1.y)];
        }
        int   nbr = __float_as_int(a0.x);
        float en  = a0.z;
        float2 v = reinterpret_cast<const float2*>(ego + (size_t)nbr * D)[lane];
        float smk = (kf == 0) ? s0.x : (kf == 1) ? s0.y : (kf == 2) ? s0.z : s0.w;
        float w = en * smk;
        acc.x += w * v.x;
        acc.y += w * v.y;
        a0 = a1; s0 = s1;
    }

    reinterpret_cast<float2*>(xn + (size_t)gw * D)[lane] = acc;

    // per-factor inverse norm (groups of 8 lanes)
    float ss = acc.x * acc.x + acc.y * acc.y;
    ss += __shfl_xor_sync(0xFFFFFFFF, ss, 1);
    ss += __shfl_xor_sync(0xFFFFFFFF, ss, 2);
    ss += __shfl_xor_sync(0xFFFFFFFF, ss, 4);
    float rinv = 1.0f / fmaxf(sqrtf(ss), 1e-12f);
    if ((lane & 7) == 0) g_rn[gw * NF + kf] = rinv;

    if (LAST) {
        float2* ap = reinterpret_cast<float2*>(g_all + (size_t)gw * D) + lane;
        float2 av = *ap;
        av.x += acc.x; av.y += acc.y;
        *ap = av;
        float2 t;
        t.x = tanhf(acc.x * rinv);
        t.y = tanhf(acc.y * rinv);
        reinterpret_cast<float2*>(tv_next + (size_t)gw * D)[lane] = t;
    }
}

// routing-score update, one warp per original edge:
// S[j] = Ssm[j] + rn[row]_k * dot(xn[row,k,:], tv[col,k,:])
__global__ void k_score(const float* __restrict__ xn, const float* __restrict__ tv,
                        const int* __restrict__ ei) {
    int gw = (blockIdx.x * blockDim.x + threadIdx.x) >> 5;
    if (gw >= NE) return;
    int lane = threadIdx.x & 31;
    int r = ei[gw];
    int c = ei[NE + gw];
    float2 a = reinterpret_cast<const float2*>(xn + (size_t)r * D)[lane];
    float2 b = reinterpret_cast<const float2*>(tv + (size_t)c * D)[lane];
    float p = a.x * b.x + a.y * b.y;
    p += __shfl_xor_sync(0xFFFFFFFF, p, 1);
    p += __shfl_xor_sync(0xFFFFFFFF, p, 2);
    p += __shfl_xor_sync(0xFFFFFFFF, p, 4);
    float p0 = __shfl_sync(0xFFFFFFFF, p, 0);
    float p1 = __shfl_sync(0xFFFFFFFF, p, 8);
    float p2 = __shfl_sync(0xFFFFFFFF, p, 16);
    float p3 = __shfl_sync(0xFFFFFFFF, p, 24);
    if (lane == 0) {
        float4 rn = *reinterpret_cast<const float4*>(g_rn + (size_t)r * NF);
        float4 sv = g_Ssm4[gw];
        sv.x += p0 * rn.x;
        sv.y += p1 * rn.y;
        sv.z += p2 * rn.z;
        sv.w += p3 * rn.w;
        g_S4[gw] = sv;
    }
}

// output S transpose [NE,4] -> [4,NE]
__global__ void k_transS_out(float* __restrict__ outS) {
    int j = blockIdx.x * blockDim.x + threadIdx.x;
    if (j >= NE) return;
    float4 s = g_S4[j];
    outS[j]          = s.x;
    outS[NE + j]     = s.y;
    outS[2 * NE + j] = s.z;
    outS[3 * NE + j] = s.w;
}

// ---------------- host orchestration ----------------

extern "C" void kernel_launch(void* const* d_in, const int* in_sizes, int n_in,
                              void* d_out, int out_size) {
    const float* user = (const float*)d_in[0];
    const float* item = (const float*)d_in[1];
    const float* Sin  = (const float*)d_in[2];
    const int*   ei   = (const int*)d_in[3];
    float* out = (float*)d_out;

    void *p_deg, *p_cnt, *p_ego0, *p_ego1, *p_all, *p_tv0, *p_tv1;
    cudaGetSymbolAddress(&p_deg,  g_deg);
    cudaGetSymbolAddress(&p_cnt,  g_cnt);
    cudaGetSymbolAddress(&p_ego0, g_ego0);
    cudaGetSymbolAddress(&p_ego1, g_ego1);
    cudaGetSymbolAddress(&p_all,  g_all);
    cudaGetSymbolAddress(&p_tv0,  g_tv0);
    cudaGetSymbolAddress(&p_tv1,  g_tv1);

    const int T = 256;
    const int gElem  = (NN * D + T - 1) / T;
    const int gNode  = (NN + T - 1) / T;
    const int gEdge  = (NE + T - 1) / T;
    const int gDir   = (2 * NE + T - 1) / T;
    const int gEdgeW = (NE * 32 + T - 1) / T;
    const int gNodeW = (NN * 32 + T - 1) / T;

    // ---- setup ----
    cudaMemsetAsync(p_deg, 0, NN * sizeof(int), 0);
    cudaMemsetAsync(p_cnt, 0, NN * sizeof(int), 0);
    k_initego<<<gElem, T>>>(user, item);
    k_transS_in<<<gEdge, T>>>(Sin);
    k_deg<<<gEdge, T>>>(ei);
    k_dinv<<<gNode, T>>>();
    k_partial<<<NBLK, 1024>>>();
    k_scanblocks<<<1, 1>>>();
    k_offsets<<<NBLK, 1024>>>();
    k_fill<<<gDir, T>>>(ei);
    k_tv0<<<gNodeW, T>>>();

    // ---- 2 layers x 2 routing iterations ----
    float* ego = (float*)p_ego0;
    float* xn  = (float*)p_ego1;
    float* tv  = (float*)p_tv0;
    float* tvn = (float*)p_tv1;
    for (int layer = 0; layer < 2; layer++) {
        for (int it = 0; it < 2; it++) {
            k_softmax<<<gEdge, T>>>();                      // E threads, once per edge
            if (it == 1)
                k_conv<true><<<gNodeW, T>>>(ego, xn, tvn);  // writes NEXT tv buffer
            else
                k_conv<false><<<gNodeW, T>>>(ego, xn, tvn);
            k_score<<<gEdgeW, T>>>(xn, tv, ei);             // reads CURRENT tv
        }
        float* t = ego; ego = xn; xn = t;
        t = tv; tv = tvn; tvn = t;
    }

    // ---- output: [user_all | item_all | S(4,NE)] ----
    cudaMemcpyAsync(out, p_all, (size_t)NN * D * sizeof(float),
                    cudaMemcpyDeviceToDevice, 0);
    k_transS_out<<<gEdge, T>>>(out + (size_t)NN * D);
}